// round 1
// baseline (speedup 1.0000x reference)
#include <cuda_runtime.h>
#include <math.h>

#define BB   16
#define NN   8400
#define NCLS 80
#define MM   32
#define RMv  16
#define KMAX 10
#define EPSF 1e-7f

// ---------------- scratch (module-static device memory, no runtime alloc) ----
__device__ float  g_bbox[(size_t)BB * NN * 4];
__device__ float  g_align[(size_t)BB * MM * NN];
__device__ int    g_mi[BB * NN];
__device__ int    g_topk[BB * MM * KMAX];
__device__ int    g_assign[BB * NN];
__device__ float  g_mpos[BB * NN];
__device__ double g_acc[8];   // [branch*4 + {bce, box, dfl, npos}]

// ---------------- init ------------------------------------------------------
__global__ void init_acc_kernel() {
    if (threadIdx.x < 8) g_acc[threadIdx.x] = 0.0;
}

// ---------------- decode: softmax-expectation -> bboxes ---------------------
__global__ void decode_kernel(const float* __restrict__ regs,
                              const float* __restrict__ anchors,
                              const float* __restrict__ strides) {
    int idx = blockIdx.x * blockDim.x + threadIdx.x;   // b*NN + n
    if (idx >= BB * NN) return;
    int n = idx % NN;
    const float* r = regs + (size_t)idx * 64;
    float d[4];
#pragma unroll
    for (int g = 0; g < 4; g++) {
        float mx = -1e30f;
#pragma unroll
        for (int j = 0; j < RMv; j++) mx = fmaxf(mx, r[g * RMv + j]);
        float se = 0.f, sw = 0.f;
#pragma unroll
        for (int j = 0; j < RMv; j++) {
            float e = expf(r[g * RMv + j] - mx);
            se += e;
            sw += e * (float)j;
        }
        d[g] = sw / se;
    }
    float ax = anchors[2 * n], ay = anchors[2 * n + 1], s = strides[n];
    float* o = g_bbox + (size_t)idx * 4;
    o[0] = ax - d[0] * s;
    o[1] = ay - d[1] * s;
    o[2] = ax + d[2] * s;
    o[3] = ay + d[3] * s;
    // reset per-branch assignment state (fused here, runs before scatter)
    g_assign[idx] = 0;
    g_mpos[idx]   = 0.f;
}

// ---------------- align metric + argmax over M -------------------------------
__global__ void align_kernel(const float* __restrict__ cls,
                             const int* __restrict__ gl,
                             const float* __restrict__ gb,
                             const float* __restrict__ anchors) {
    int idx = blockIdx.x * blockDim.x + threadIdx.x;
    if (idx >= BB * NN) return;
    int b = idx / NN, n = idx % NN;
    const float* p = g_bbox + (size_t)idx * 4;
    float p1x = p[0], p1y = p[1], p2x = p[2], p2y = p[3];
    float pa = (p2x - p1x) * (p2y - p1y);
    float ax = anchors[2 * n], ay = anchors[2 * n + 1];
    const float* xr = cls + (size_t)idx * NCLS;
    float best = -1.f; int bm = 0;
    for (int m = 0; m < MM; m++) {
        const float* g = gb + ((size_t)(b * MM + m)) * 4;
        float g1x = g[0], g1y = g[1], g2x = g[2], g2y = g[3];
        float iw = fmaxf(fminf(p2x, g2x) - fmaxf(p1x, g1x), 0.f);
        float ih = fmaxf(fminf(p2y, g2y) - fmaxf(p1y, g1y), 0.f);
        float inter = iw * ih;
        float ga  = (g2x - g1x) * (g2y - g1y);
        float uni = pa + ga - inter + EPSF;
        float iou = inter / uni;
        int   lab = gl[b * MM + m];
        float x   = xr[lab];
        float sc  = 1.f / (1.f + expf(-x));
        float ing = (ax >= g1x && ax <= g2x && ay >= g1y && ay <= g2y) ? 1.f : 0.f;
        float a   = sc * powf(iou, 6.0f) * ing;
        g_align[((size_t)(b * MM + m)) * NN + n] = a;
        if (a > best) { best = a; bm = m; }   // strict > : first-occurrence argmax
    }
    g_mi[idx] = bm;
}

// ---------------- top-k with jax tie semantics (value desc, index asc) -------
__global__ void topk_kernel(const float* __restrict__ mg, int K) {
    int bm = blockIdx.x;                           // b*MM + m
    const float* row = g_align + (size_t)bm * NN;
    __shared__ unsigned long long sk[256];
    __shared__ int sel[KMAX];
    int tid = threadIdx.x;
    float mgv = mg[bm];
    for (int k = 0; k < K; k++) {
        unsigned long long best = 0;
        for (int n = tid; n < NN; n += 256) {
            bool skip = false;
            for (int j = 0; j < k; j++) if (sel[j] == n) skip = true;
            if (skip) continue;
            unsigned long long key =
                ((unsigned long long)__float_as_uint(row[n]) << 32) |
                (unsigned long long)(0xFFFFFFFFu - (unsigned)n);
            if (key > best) best = key;
        }
        sk[tid] = best;
        __syncthreads();
        for (int st = 128; st > 0; st >>= 1) {
            if (tid < st) { if (sk[tid + st] > sk[tid]) sk[tid] = sk[tid + st]; }
            __syncthreads();
        }
        if (tid == 0) {
            int n = (int)(0xFFFFFFFFu - (unsigned)(sk[0] & 0xFFFFFFFFull));
            sel[k] = n;
            g_topk[bm * KMAX + k] = (mgv > 0.f) ? n : -1;
        }
        __syncthreads();
    }
}

// ---------------- scatter assignment (unique per anchor via mask_single) -----
__global__ void scatter_kernel(int K) {
    int idx = blockIdx.x * blockDim.x + threadIdx.x;
    if (idx >= BB * MM * K) return;
    int k  = idx % K;
    int bm = idx / K;
    int b = bm / MM, m = bm % MM;
    int n = g_topk[bm * KMAX + k];
    if (n < 0) return;
    if (g_mi[b * NN + n] == m) {
        g_assign[b * NN + n] = m;
        g_mpos[b * NN + n]   = 1.f;
    }
}

// ---------------- loss: BCE + CIoU + DFL, block-reduced, fp64 atomics --------
__global__ void loss_kernel(const float* __restrict__ cls,
                            const float* __restrict__ regs,
                            const float* __restrict__ anchors,
                            const float* __restrict__ strides,
                            const int* __restrict__ gl,
                            const float* __restrict__ gb,
                            int br) {
    int idx = blockIdx.x * blockDim.x + threadIdx.x;
    float bce = 0.f, lbox = 0.f, ldfl = 0.f, np = 0.f;
    if (idx < BB * NN) {
        int b = idx / NN, n = idx % NN;
        float fg = g_mpos[idx];
        int   m  = g_assign[idx];
        int tlab = (fg > 0.f) ? gl[b * MM + m] : 0;
        const float* gt = gb + ((size_t)(b * MM + m)) * 4;
        float t1x = gt[0] * fg, t1y = gt[1] * fg, t2x = gt[2] * fg, t2y = gt[3] * fg;
        const float* p = g_bbox + (size_t)idx * 4;
        float p1x = p[0], p1y = p[1], p2x = p[2], p2y = p[3];
        // plain IoU vs target box
        float iw = fmaxf(fminf(p2x, t2x) - fmaxf(p1x, t1x), 0.f);
        float ih = fmaxf(fminf(p2y, t2y) - fmaxf(p1y, t1y), 0.f);
        float inter = iw * ih;
        float w1 = p2x - p1x, h1 = p2y - p1y;
        float w2 = t2x - t1x, h2 = t2y - t1y;
        float uni = w1 * h1 + w2 * h2 - inter + EPSF;
        float iou = inter / uni;
        float t   = iou * fg;
        // BCE over all classes (target nonzero only at tlab when fg)
        const float* xr = cls + (size_t)idx * NCLS;
#pragma unroll 4
        for (int c = 0; c < NCLS; c++) {
            float x = xr[c];
            bce += fmaxf(x, 0.f) + log1pf(expf(-fabsf(x)));
        }
        bce -= xr[tlab] * t;
        np = fg;
        if (fg > 0.f) {
            // CIoU -- replicates reference bug: ch = max(p2y,t2y) - min(p1y,p1y)
            float cw = fmaxf(p2x, t2x) - fminf(p1x, t1x);
            float ch = fmaxf(p2y, t2y) - p1y;
            float c2 = cw * cw + ch * ch + EPSF;
            float dx = p1x + p2x - t1x - t2x;
            float dy = p1y + p2y - t1y - t2y;
            float rho2 = (dx * dx + dy * dy) * 0.25f;
            const float pi2 = 9.869604401089358f;
            float dv = atanf(w2 / (h2 + EPSF)) - atanf(w1 / (h1 + EPSF));
            float v  = (4.0f / pi2) * dv * dv;
            float alpha = v / (v - iou + (1.0f + EPSF));
            float ciou  = iou - (rho2 / c2 + v * alpha);
            lbox = 1.0f - ciou;
            // DFL
            float s  = strides[n];
            float ax = anchors[2 * n], ay = anchors[2 * n + 1];
            float tt[4] = { (ax - t1x) / s, (ay - t1y) / s,
                            (t2x - ax) / s, (t2y - ay) / s };
            const float* r = regs + (size_t)idx * 64;
#pragma unroll
            for (int g = 0; g < 4; g++) {
                float v0 = fminf(fmaxf(tt[g], 0.f), 14.99f);
                int   tl = (int)v0;
                float wl = (float)(tl + 1) - v0;
                float wr = 1.0f - wl;
                float mx = -1e30f;
#pragma unroll
                for (int j = 0; j < RMv; j++) mx = fmaxf(mx, r[g * RMv + j]);
                float se = 0.f;
#pragma unroll
                for (int j = 0; j < RMv; j++) se += expf(r[g * RMv + j] - mx);
                float lse = logf(se) + mx;
                float lpl = r[g * RMv + tl]     - lse;
                float lpr = r[g * RMv + tl + 1] - lse;
                ldfl += -lpl * wl - lpr * wr;
            }
        }
    }
    // block reduce 4 quantities, fp64 global accumulation
    __shared__ float sh[256];
    float vals[4] = { bce, lbox, ldfl, np };
    double* acc = g_acc + br * 4;
    for (int q = 0; q < 4; q++) {
        sh[threadIdx.x] = vals[q];
        __syncthreads();
        for (int st = 128; st > 0; st >>= 1) {
            if (threadIdx.x < st) sh[threadIdx.x] += sh[threadIdx.x + st];
            __syncthreads();
        }
        if (threadIdx.x == 0) atomicAdd(&acc[q], (double)sh[0]);
        __syncthreads();
    }
}

// ---------------- finalize ----------------------------------------------------
__global__ void final_kernel(float* __restrict__ out) {
    double t[2], c[2], bx[2], df[2];
    for (int br = 0; br < 2; br++) {
        double bce  = g_acc[br * 4 + 0];
        double lbox = g_acc[br * 4 + 1];
        double ldfl = g_acc[br * 4 + 2];
        double npos = g_acc[br * 4 + 3];
        double nfg  = fmax(npos, 1.0);
        c[br]  = bce / nfg;          // divisor max(mpos.sum(),1) == max(fg.sum(),1)
        bx[br] = lbox / nfg;
        df[br] = ldfl / (nfg * 4.0);
        t[br]  = c[br] * 1.0 + bx[br] * 7.5 + df[br] * 1.5;
    }
    out[0] = (float)(t[0] + t[1]);
    out[1] = (float)(c[0] + c[1]);
    out[2] = (float)(bx[0] + bx[1]);
    out[3] = (float)(df[0] + df[1]);
    out[4] = (float)t[0];
    out[5] = (float)t[1];
}

// ---------------- launch -------------------------------------------------------
extern "C" void kernel_launch(void* const* d_in, const int* in_sizes, int n_in,
                              void* d_out, int out_size) {
    const float* cls0    = (const float*)d_in[0];
    const float* reg0    = (const float*)d_in[1];
    const float* cls1    = (const float*)d_in[2];
    const float* reg1    = (const float*)d_in[3];
    const float* anchors = (const float*)d_in[4];
    const float* strides = (const float*)d_in[5];
    const int*   gl      = (const int*)d_in[6];
    const float* gb      = (const float*)d_in[7];
    const float* mg      = (const float*)d_in[8];
    float* out = (float*)d_out;

    const int BN = BB * NN;
    init_acc_kernel<<<1, 8>>>();
    for (int br = 0; br < 2; br++) {
        const float* cls  = br ? cls1 : cls0;
        const float* regs = br ? reg1 : reg0;
        int K = br ? 1 : 10;
        decode_kernel<<<(BN + 255) / 256, 256>>>(regs, anchors, strides);
        align_kernel<<<(BN + 255) / 256, 256>>>(cls, gl, gb, anchors);
        topk_kernel<<<BB * MM, 256>>>(mg, K);
        scatter_kernel<<<(BB * MM * K + 255) / 256, 256>>>(K);
        loss_kernel<<<(BN + 255) / 256, 256>>>(cls, regs, anchors, strides, gl, gb, br);
    }
    final_kernel<<<1, 1>>>(out);
}

// round 2
// speedup vs baseline: 2.1339x; 2.1339x over previous
#include <cuda_runtime.h>
#include <math.h>

#define BB   16
#define NN   8400
#define NCLS 80
#define MM   32
#define RMv  16
#define KMAX 10
#define EPSF 1e-7f
#define BN   (BB * NN)

typedef unsigned long long ull;

// ---------------- scratch (per-branch doubled) -------------------------------
__device__ float  g_bbox[2 * (size_t)BN * 4];
__device__ float  g_align[2 * (size_t)BB * MM * NN];
__device__ int    g_mi[2 * BN];
__device__ int    g_topk[2 * BB * MM * KMAX];
__device__ int    g_assign[2 * BN];
__device__ float  g_mpos[2 * BN];
__device__ double g_acc[8];   // [branch*4 + {bce, box, dfl, npos}]

// ---------------- block reduce helpers ---------------------------------------
__device__ __forceinline__ float warpSum(float v) {
#pragma unroll
    for (int o = 16; o > 0; o >>= 1) v += __shfl_down_sync(0xffffffffu, v, o);
    return v;
}

// ---------------- decode: thread per (br, anchor, group) ----------------------
__global__ void decode_kernel(const float* __restrict__ reg0,
                              const float* __restrict__ reg1,
                              const float* __restrict__ anchors,
                              const float* __restrict__ strides) {
    int t = blockIdx.x * blockDim.x + threadIdx.x;   // over BN*4
    int br = blockIdx.y;
    if (blockIdx.x == 0 && br == 0 && threadIdx.x < 8) g_acc[threadIdx.x] = 0.0;
    if (t >= BN * 4) return;
    int g   = t & 3;
    int idx = t >> 2;          // b*NN + n
    int n   = idx % NN;
    const float* regs = br ? reg1 : reg0;
    const float4* r4 = (const float4*)(regs + (size_t)idx * 64 + g * RMv);
    float4 a0 = r4[0], a1 = r4[1], a2 = r4[2], a3 = r4[3];
    float v[16] = { a0.x,a0.y,a0.z,a0.w, a1.x,a1.y,a1.z,a1.w,
                    a2.x,a2.y,a2.z,a2.w, a3.x,a3.y,a3.z,a3.w };
    float mx = v[0];
#pragma unroll
    for (int j = 1; j < 16; j++) mx = fmaxf(mx, v[j]);
    float se = 0.f, sw = 0.f;
#pragma unroll
    for (int j = 0; j < 16; j++) {
        float e = __expf(v[j] - mx);
        se += e; sw += e * (float)j;
    }
    float d = sw / se;
    float s = strides[n];
    float a = (g & 1) ? anchors[2 * n + 1] : anchors[2 * n];
    g_bbox[(size_t)br * BN * 4 + (size_t)idx * 4 + g] = (g < 2) ? (a - d * s) : (a + d * s);
    if (g == 0) { g_assign[br * BN + idx] = 0; g_mpos[br * BN + idx] = 0.f; }
}

// ---------------- align metric + argmax over M --------------------------------
__global__ void align_kernel(const float* __restrict__ cls0,
                             const float* __restrict__ cls1,
                             const int* __restrict__ gl,
                             const float* __restrict__ gb,
                             const float* __restrict__ anchors) {
    int idx = blockIdx.x * blockDim.x + threadIdx.x;
    int br  = blockIdx.y;
    if (idx >= BN) return;
    int b = idx / NN, n = idx % NN;
    const float* cls = br ? cls1 : cls0;
    const float* p = g_bbox + (size_t)br * BN * 4 + (size_t)idx * 4;
    float p1x = p[0], p1y = p[1], p2x = p[2], p2y = p[3];
    float pa = (p2x - p1x) * (p2y - p1y);
    float ax = anchors[2 * n], ay = anchors[2 * n + 1];
    const float* xr = cls + (size_t)idx * NCLS;
    float* arow = g_align + (size_t)br * BB * MM * NN;
    float best = -1.f; int bm = 0;
#pragma unroll 4
    for (int m = 0; m < MM; m++) {
        const float* g = gb + ((size_t)(b * MM + m)) * 4;
        float g1x = g[0], g1y = g[1], g2x = g[2], g2y = g[3];
        float iw = fmaxf(fminf(p2x, g2x) - fmaxf(p1x, g1x), 0.f);
        float ih = fmaxf(fminf(p2y, g2y) - fmaxf(p1y, g1y), 0.f);
        float inter = iw * ih;
        float ga  = (g2x - g1x) * (g2y - g1y);
        float uni = pa + ga - inter + EPSF;
        float iou = inter / uni;
        float i2 = iou * iou;
        float i6 = i2 * i2 * i2;
        int   lab = gl[b * MM + m];
        float x   = xr[lab];
        float sc  = 1.f / (1.f + __expf(-x));
        float ing = (ax >= g1x && ax <= g2x && ay >= g1y && ay <= g2y) ? 1.f : 0.f;
        float a   = sc * i6 * ing;
        arow[((size_t)(b * MM + m)) * NN + n] = a;
        if (a > best) { best = a; bm = m; }   // strict > : first occurrence
    }
    g_mi[br * BN + idx] = bm;
}

// ---------------- top-k: single pass, per-thread sorted list + tournament -----
__global__ void topk_kernel(const float* __restrict__ mg) {
    int bid = blockIdx.x;            // 0..1023
    int br  = bid >> 9;
    int bm  = bid & 511;
    int K   = br ? 1 : KMAX;
    const float* row = g_align + (size_t)br * BB * MM * NN + (size_t)bm * NN;
    int tid  = threadIdx.x;
    int lane = tid & 31, wid = tid >> 5;

    ull loc[KMAX];
#pragma unroll
    for (int j = 0; j < KMAX; j++) loc[j] = 0ull;

    for (int n = tid; n < NN; n += 256) {
        ull key = ((ull)__float_as_uint(row[n]) << 32) |
                  (ull)(0xFFFFFFFFu - (unsigned)n);
        if (key > loc[KMAX - 1]) {
            loc[KMAX - 1] = key;
#pragma unroll
            for (int j = KMAX - 1; j > 0; j--) {
                if (loc[j] > loc[j - 1]) { ull tmp = loc[j - 1]; loc[j - 1] = loc[j]; loc[j] = tmp; }
            }
        }
    }

    __shared__ ull s[256 * KMAX];
    __shared__ ull warpmax[8];
    __shared__ ull swin;
#pragma unroll
    for (int j = 0; j < KMAX; j++) s[tid * KMAX + j] = loc[j];
    __syncthreads();

    float mgv = mg[bm];
    int ptr = 0;
    int*  tk = g_topk + br * BB * MM * KMAX + bm * KMAX;
    for (int k = 0; k < K; k++) {
        ull h = (ptr < KMAX) ? s[tid * KMAX + ptr] : 0ull;
        ull w = h;
#pragma unroll
        for (int o = 16; o > 0; o >>= 1) {
            ull other = __shfl_down_sync(0xffffffffu, w, o);
            if (other > w) w = other;
        }
        if (lane == 0) warpmax[wid] = w;
        __syncthreads();
        if (tid < 8) {
            ull v = warpmax[tid];
#pragma unroll
            for (int o = 4; o > 0; o >>= 1) {
                ull other = __shfl_down_sync(0xffu, v, o);
                if (other > v) v = other;
            }
            if (tid == 0) swin = v;
        }
        __syncthreads();
        ull win = swin;
        if (h == win && h != 0ull) ptr++;
        if (tid == 0) {
            int n = (int)(0xFFFFFFFFu - (unsigned)(win & 0xFFFFFFFFull));
            tk[k] = (mgv > 0.f) ? n : -1;
        }
        __syncthreads();
    }
}

// ---------------- scatter assignment ------------------------------------------
__global__ void scatter_kernel() {
    int t = blockIdx.x * blockDim.x + threadIdx.x;   // over 2*BB*MM*KMAX
    if (t >= 2 * BB * MM * KMAX) return;
    int k  = t % KMAX;
    int bm = (t / KMAX) % (BB * MM);
    int br = t / (KMAX * BB * MM);
    int K  = br ? 1 : KMAX;
    if (k >= K) return;
    int b = bm / MM, m = bm % MM;
    int n = g_topk[br * BB * MM * KMAX + bm * KMAX + k];
    if (n < 0) return;
    if (g_mi[br * BN + b * NN + n] == m) {
        g_assign[br * BN + b * NN + n] = m;
        g_mpos[br * BN + b * NN + n]   = 1.f;
    }
}

// ---------------- BCE: coalesced elementwise softplus sum ---------------------
__global__ void bce_kernel(const float* __restrict__ cls0,
                           const float* __restrict__ cls1) {
    int br = blockIdx.y;
    const float4* cls = (const float4*)(br ? cls1 : cls0);
    size_t i = (size_t)blockIdx.x * blockDim.x + threadIdx.x;
    float acc = 0.f;
    const size_t NV = (size_t)BN * NCLS / 4;   // 2,688,000
    if (i < NV) {
        float4 v = cls[i];
        float xs[4] = { v.x, v.y, v.z, v.w };
#pragma unroll
        for (int j = 0; j < 4; j++) {
            float x = xs[j];
            acc += fmaxf(x, 0.f) + __logf(1.f + __expf(-fabsf(x)));
        }
    }
    // block reduce
    acc = warpSum(acc);
    __shared__ float sh[8];
    if ((threadIdx.x & 31) == 0) sh[threadIdx.x >> 5] = acc;
    __syncthreads();
    if (threadIdx.x < 8) {
        float v = sh[threadIdx.x];
#pragma unroll
        for (int o = 4; o > 0; o >>= 1) v += __shfl_down_sync(0xffu, v, o);
        if (threadIdx.x == 0) atomicAdd(&g_acc[br * 4 + 0], (double)v);
    }
}

// ---------------- per-anchor loss: iou target term, CIoU, DFL -----------------
__global__ void loss_kernel(const float* __restrict__ cls0,
                            const float* __restrict__ cls1,
                            const float* __restrict__ reg0,
                            const float* __restrict__ reg1,
                            const float* __restrict__ anchors,
                            const float* __restrict__ strides,
                            const int* __restrict__ gl,
                            const float* __restrict__ gb) {
    int idx = blockIdx.x * blockDim.x + threadIdx.x;
    int br  = blockIdx.y;
    float bce = 0.f, lbox = 0.f, ldfl = 0.f, np = 0.f;
    if (idx < BN) {
        int b = idx / NN, n = idx % NN;
        float fg = g_mpos[br * BN + idx];
        int   m  = g_assign[br * BN + idx];
        const float* gt = gb + ((size_t)(b * MM + m)) * 4;
        float t1x = gt[0] * fg, t1y = gt[1] * fg, t2x = gt[2] * fg, t2y = gt[3] * fg;
        const float* p = g_bbox + (size_t)br * BN * 4 + (size_t)idx * 4;
        float p1x = p[0], p1y = p[1], p2x = p[2], p2y = p[3];
        float iw = fmaxf(fminf(p2x, t2x) - fmaxf(p1x, t1x), 0.f);
        float ih = fmaxf(fminf(p2y, t2y) - fmaxf(p1y, t1y), 0.f);
        float inter = iw * ih;
        float w1 = p2x - p1x, h1 = p2y - p1y;
        float w2 = t2x - t1x, h2 = t2y - t1y;
        float uni = w1 * h1 + w2 * h2 - inter + EPSF;
        float iou = inter / uni;
        np = fg;
        if (fg > 0.f) {
            const float* cls = br ? cls1 : cls0;
            int tlab = gl[b * MM + m];
            bce = -cls[(size_t)idx * NCLS + tlab] * iou;   // target term of BCE
            // CIoU (replicates reference bug: ch = max(p2y,t2y) - p1y)
            float cw = fmaxf(p2x, t2x) - fminf(p1x, t1x);
            float ch = fmaxf(p2y, t2y) - p1y;
            float c2 = cw * cw + ch * ch + EPSF;
            float dx = p1x + p2x - t1x - t2x;
            float dy = p1y + p2y - t1y - t2y;
            float rho2 = (dx * dx + dy * dy) * 0.25f;
            const float pi2 = 9.869604401089358f;
            float dv = atanf(w2 / (h2 + EPSF)) - atanf(w1 / (h1 + EPSF));
            float v  = (4.0f / pi2) * dv * dv;
            float alpha = v / (v - iou + (1.0f + EPSF));
            lbox = 1.0f - (iou - (rho2 / c2 + v * alpha));
            // DFL
            const float* regs = br ? reg1 : reg0;
            float s  = strides[n];
            float ax = anchors[2 * n], ay = anchors[2 * n + 1];
            float tt[4] = { (ax - t1x) / s, (ay - t1y) / s,
                            (t2x - ax) / s, (t2y - ay) / s };
            const float* r = regs + (size_t)idx * 64;
#pragma unroll
            for (int g = 0; g < 4; g++) {
                float v0 = fminf(fmaxf(tt[g], 0.f), 14.99f);
                int   tl = (int)v0;
                float wl = (float)(tl + 1) - v0;
                float wr = 1.0f - wl;
                float mx = -1e30f;
#pragma unroll
                for (int j = 0; j < RMv; j++) mx = fmaxf(mx, r[g * RMv + j]);
                float se = 0.f;
#pragma unroll
                for (int j = 0; j < RMv; j++) se += __expf(r[g * RMv + j] - mx);
                float lse = __logf(se) + mx;
                ldfl += -(r[g * RMv + tl]     - lse) * wl
                        -(r[g * RMv + tl + 1] - lse) * wr;
            }
        }
    }
    float vals[4] = { bce, lbox, ldfl, np };
    __shared__ float sh[8];
#pragma unroll
    for (int q = 0; q < 4; q++) {
        float v = warpSum(vals[q]);
        if ((threadIdx.x & 31) == 0) sh[threadIdx.x >> 5] = v;
        __syncthreads();
        if (threadIdx.x < 8) {
            float w = sh[threadIdx.x];
#pragma unroll
            for (int o = 4; o > 0; o >>= 1) w += __shfl_down_sync(0xffu, w, o);
            if (threadIdx.x == 0 && w != 0.f) atomicAdd(&g_acc[br * 4 + q], (double)w);
        }
        __syncthreads();
    }
}

// ---------------- finalize -----------------------------------------------------
__global__ void final_kernel(float* __restrict__ out) {
    double t[2], c[2], bx[2], df[2];
    for (int br = 0; br < 2; br++) {
        double bce  = g_acc[br * 4 + 0];
        double lbox = g_acc[br * 4 + 1];
        double ldfl = g_acc[br * 4 + 2];
        double nfg  = fmax(g_acc[br * 4 + 3], 1.0);
        c[br]  = bce / nfg;
        bx[br] = lbox / nfg;
        df[br] = ldfl / (nfg * 4.0);
        t[br]  = c[br] + bx[br] * 7.5 + df[br] * 1.5;
    }
    out[0] = (float)(t[0] + t[1]);
    out[1] = (float)(c[0] + c[1]);
    out[2] = (float)(bx[0] + bx[1]);
    out[3] = (float)(df[0] + df[1]);
    out[4] = (float)t[0];
    out[5] = (float)t[1];
}

// ---------------- launch --------------------------------------------------------
extern "C" void kernel_launch(void* const* d_in, const int* in_sizes, int n_in,
                              void* d_out, int out_size) {
    const float* cls0    = (const float*)d_in[0];
    const float* reg0    = (const float*)d_in[1];
    const float* cls1    = (const float*)d_in[2];
    const float* reg1    = (const float*)d_in[3];
    const float* anchors = (const float*)d_in[4];
    const float* strides = (const float*)d_in[5];
    const int*   gl      = (const int*)d_in[6];
    const float* gb      = (const float*)d_in[7];
    const float* mg      = (const float*)d_in[8];
    float* out = (float*)d_out;

    decode_kernel<<<dim3((BN * 4 + 255) / 256, 2), 256>>>(reg0, reg1, anchors, strides);
    align_kernel<<<dim3((BN + 255) / 256, 2), 256>>>(cls0, cls1, gl, gb, anchors);
    topk_kernel<<<1024, 256>>>(mg);
    scatter_kernel<<<(2 * BB * MM * KMAX + 255) / 256, 256>>>();
    bce_kernel<<<dim3((BN * NCLS / 4 + 255) / 256, 2), 256>>>(cls0, cls1);
    loss_kernel<<<dim3((BN + 255) / 256, 2), 256>>>(cls0, cls1, reg0, reg1,
                                                    anchors, strides, gl, gb);
    final_kernel<<<1, 1>>>(out);
}

// round 3
// speedup vs baseline: 2.1700x; 1.0169x over previous
#include <cuda_runtime.h>
#include <math.h>

#define BB    16
#define NN    8400
#define NCLS  80
#define MM    32
#define RMv   16
#define KMAX  10
#define EPSF  1e-7f
#define BN    (BB * NN)
#define TILES 263                 // ceil(8400/32)
#define LISTMAX (512 * KMAX)      // 5120 per branch

typedef unsigned long long ull;

// ---------------- scratch ------------------------------------------------------
__device__ float  g_bbox[2 * (size_t)BN * 4];
__device__ float  g_pdg[2 * (size_t)BB * MM * NN];   // sigmoid(cls[.,label_m]) per (br,b,m,n)
__device__ int    g_list[2 * LISTMAX];               // packed (b*NN+n) | (m<<18)
__device__ int    g_cnt[2];
__device__ double g_acc[8];                          // [br*4 + {bce, box, dfl, npos}]

// ---------------- helpers ------------------------------------------------------
__device__ __forceinline__ float warpSum(float v) {
#pragma unroll
    for (int o = 16; o > 0; o >>= 1) v += __shfl_down_sync(0xffffffffu, v, o);
    return v;
}

// align metric, used identically in scan and argmax-recompute (bit-exact match)
__device__ __forceinline__ float align_val(float p1x, float p1y, float p2x, float p2y,
                                           float pa, float ax, float ay,
                                           const float* __restrict__ g, float pdgv) {
    float g1x = g[0], g1y = g[1], g2x = g[2], g2y = g[3];
    float iw = fmaxf(fminf(p2x, g2x) - fmaxf(p1x, g1x), 0.f);
    float ih = fmaxf(fminf(p2y, g2y) - fmaxf(p1y, g1y), 0.f);
    float inter = iw * ih;
    float ga  = (g2x - g1x) * (g2y - g1y);
    float uni = pa + ga - inter + EPSF;
    float iou = inter / uni;
    float i2 = iou * iou;
    float i6 = i2 * i2 * i2;
    float ing = (ax >= g1x && ax <= g2x && ay >= g1y && ay <= g2y) ? 1.f : 0.f;
    return pdgv * i6 * ing;
}

// ---------------- K1: decode (thread per (br, anchor, side-group)) --------------
__global__ void decode_kernel(const float* __restrict__ reg0,
                              const float* __restrict__ reg1,
                              const float* __restrict__ anchors,
                              const float* __restrict__ strides) {
    if (blockIdx.x == 0 && blockIdx.y == 0 && threadIdx.x < 8) {
        g_acc[threadIdx.x] = 0.0;
        if (threadIdx.x < 2) g_cnt[threadIdx.x] = 0;
    }
    int t = blockIdx.x * blockDim.x + threadIdx.x;   // over BN*4
    int br = blockIdx.y;
    if (t >= BN * 4) return;
    int g   = t & 3;
    int idx = t >> 2;
    int n   = idx % NN;
    const float* regs = br ? reg1 : reg0;
    const float4* r4 = (const float4*)(regs + (size_t)idx * 64 + g * RMv);
    float4 a0 = r4[0], a1 = r4[1], a2 = r4[2], a3 = r4[3];
    float v[16] = { a0.x,a0.y,a0.z,a0.w, a1.x,a1.y,a1.z,a1.w,
                    a2.x,a2.y,a2.z,a2.w, a3.x,a3.y,a3.z,a3.w };
    float mx = v[0];
#pragma unroll
    for (int j = 1; j < 16; j++) mx = fmaxf(mx, v[j]);
    float se = 0.f, sw = 0.f;
#pragma unroll
    for (int j = 0; j < 16; j++) {
        float e = __expf(v[j] - mx);
        se += e; sw += e * (float)j;
    }
    float d = sw / se;
    float s = strides[n];
    float a = (g & 1) ? anchors[2 * n + 1] : anchors[2 * n];
    g_bbox[(size_t)br * BN * 4 + (size_t)idx * 4 + g] = (g < 2) ? (a - d * s) : (a + d * s);
}

// ---------------- K2: BCE softplus sum + label-column sigmoid transpose ---------
__global__ void bce_gather_kernel(const float* __restrict__ cls0,
                                  const float* __restrict__ cls1,
                                  const int* __restrict__ gl) {
    __shared__ float sh[32 * 81];
    __shared__ int   slab[MM];
    float acc0 = 0.f, acc1 = 0.f;
    const int ntiles = 2 * BB * TILES;
    for (int tile = blockIdx.x; tile < ntiles; tile += gridDim.x) {
        int br  = tile / (BB * TILES);
        int rem = tile % (BB * TILES);
        int b   = rem / TILES;
        int n0  = (rem % TILES) * 32;
        int na  = min(32, NN - n0);
        const float* cls = br ? cls1 : cls0;
        const float* base = cls + ((size_t)(b * NN + n0)) * NCLS;
        if (threadIdx.x < MM) slab[threadIdx.x] = gl[b * MM + threadIdx.x];
        int tot = na * NCLS;
        float a = 0.f;
        for (int i = threadIdx.x; i < tot; i += 256) {
            float x = base[i];
            a += fmaxf(x, 0.f) + __logf(1.f + __expf(-fabsf(x)));
            int an = i / NCLS, c = i - an * NCLS;
            sh[an * 81 + c] = x;
        }
        if (br) acc1 += a; else acc0 += a;
        __syncthreads();
        // gather: 1024 (m, a) pairs, warp covers a=0..31 for one m (coalesced store)
        float* pdg = g_pdg + ((size_t)(br * BB + b) * MM) * NN;
#pragma unroll
        for (int i = 0; i < 4; i++) {
            int p = threadIdx.x + i * 256;
            int m = p >> 5, an = p & 31;
            if (an < na) {
                float x = sh[an * 81 + slab[m]];
                pdg[(size_t)m * NN + n0 + an] = 1.f / (1.f + __expf(-x));
            }
        }
        __syncthreads();
    }
    // reduce both branch accumulators
    __shared__ float shr[8];
#pragma unroll
    for (int q = 0; q < 2; q++) {
        float v = warpSum(q ? acc1 : acc0);
        if ((threadIdx.x & 31) == 0) shr[threadIdx.x >> 5] = v;
        __syncthreads();
        if (threadIdx.x < 8) {
            float w = shr[threadIdx.x];
#pragma unroll
            for (int o = 4; o > 0; o >>= 1) w += __shfl_down_sync(0xffu, w, o);
            if (threadIdx.x == 0 && w != 0.f) atomicAdd(&g_acc[q * 4 + 0], (double)w);
        }
        __syncthreads();
    }
}

// ---------------- K3: fused on-the-fly align + top-k + inline scatter -----------
__global__ void topk_fused_kernel(const float* __restrict__ anchors,
                                  const float* __restrict__ gb,
                                  const float* __restrict__ mg) {
    int bid = blockIdx.x;            // 0..1023
    int br  = bid >> 9;
    int bm  = bid & 511;             // b*MM + m
    int b   = bm >> 5, m = bm & 31;
    int K   = br ? 1 : KMAX;
    int tid  = threadIdx.x;
    int lane = tid & 31, wid = tid >> 5;

    const float4* bbox4 = (const float4*)g_bbox + (size_t)br * BN + (size_t)b * NN;
    const float2* anc2  = (const float2*)anchors;
    const float*  pdg   = g_pdg + ((size_t)(br * BB + b) * MM + m) * NN;
    const float*  gt    = gb + (size_t)bm * 4;

    ull loc[KMAX];
#pragma unroll
    for (int j = 0; j < KMAX; j++) loc[j] = 0ull;

    for (int n = tid; n < NN; n += 256) {
        float4 p = bbox4[n];
        float pa = (p.z - p.x) * (p.w - p.y);
        float2 an = anc2[n];
        float a = align_val(p.x, p.y, p.z, p.w, pa, an.x, an.y, gt, pdg[n]);
        ull key = ((ull)__float_as_uint(a) << 32) |
                  (ull)(0xFFFFFFFFu - (unsigned)n);
        if (key > loc[KMAX - 1]) {
            loc[KMAX - 1] = key;
#pragma unroll
            for (int j = KMAX - 1; j > 0; j--) {
                if (loc[j] > loc[j - 1]) { ull t2 = loc[j - 1]; loc[j - 1] = loc[j]; loc[j] = t2; }
            }
        }
    }

    __shared__ ull s[256 * KMAX];
    __shared__ ull warpmax[8];
    __shared__ ull swin;
    __shared__ int sel[KMAX];
#pragma unroll
    for (int j = 0; j < KMAX; j++) s[tid * KMAX + j] = loc[j];
    __syncthreads();

    int ptr = 0;
    for (int k = 0; k < K; k++) {
        ull h = (ptr < KMAX) ? s[tid * KMAX + ptr] : 0ull;
        ull w = h;
#pragma unroll
        for (int o = 16; o > 0; o >>= 1) {
            ull other = __shfl_down_sync(0xffffffffu, w, o);
            if (other > w) w = other;
        }
        if (lane == 0) warpmax[wid] = w;
        __syncthreads();
        if (tid < 8) {
            ull v = warpmax[tid];
#pragma unroll
            for (int o = 4; o > 0; o >>= 1) {
                ull other = __shfl_down_sync(0xffu, v, o);
                if (other > v) v = other;
            }
            if (tid == 0) swin = v;
        }
        __syncthreads();
        ull win = swin;
        if (h == win && h != 0ull) ptr++;
        if (tid == 0) sel[k] = (int)(0xFFFFFFFFu - (unsigned)(win & 0xFFFFFFFFull));
        __syncthreads();
    }

    // inline scatter: candidate passes iff it's the argmax GT for that anchor
    if (tid < K && mg[bm] > 0.f) {
        int n = sel[tid];
        float4 p = bbox4[n];
        float pa = (p.z - p.x) * (p.w - p.y);
        float2 an = anc2[n];
        const float* pdgb = g_pdg + ((size_t)(br * BB + b) * MM) * NN;
        float best = -1.f; int bmx = 0;
#pragma unroll 4
        for (int mp = 0; mp < MM; mp++) {
            float a = align_val(p.x, p.y, p.z, p.w, pa, an.x, an.y,
                                gb + ((size_t)(b * MM + mp)) * 4,
                                pdgb[(size_t)mp * NN + n]);
            if (a > best) { best = a; bmx = mp; }   // first-occurrence argmax
        }
        if (bmx == m) {
            int pos = atomicAdd(&g_cnt[br], 1);
            g_list[br * LISTMAX + pos] = (b * NN + n) | (m << 18);
        }
    }
}

// ---------------- K4: loss over compact positive list ---------------------------
__global__ void loss_list_kernel(const float* __restrict__ cls0,
                                 const float* __restrict__ cls1,
                                 const float* __restrict__ reg0,
                                 const float* __restrict__ reg1,
                                 const float* __restrict__ anchors,
                                 const float* __restrict__ strides,
                                 const int* __restrict__ gl,
                                 const float* __restrict__ gb) {
    int br  = blockIdx.y;
    int i   = blockIdx.x * blockDim.x + threadIdx.x;
    int cnt = g_cnt[br];
    float bce = 0.f, lbox = 0.f, ldfl = 0.f, np = 0.f;
    if (i < cnt) {
        int pack = g_list[br * LISTMAX + i];
        int idx = pack & 0x3FFFF;          // b*NN + n
        int m   = pack >> 18;
        int b = idx / NN, n = idx % NN;
        np = 1.f;
        const float* gt = gb + ((size_t)(b * MM + m)) * 4;
        float t1x = gt[0], t1y = gt[1], t2x = gt[2], t2y = gt[3];
        const float* p = g_bbox + (size_t)br * BN * 4 + (size_t)idx * 4;
        float p1x = p[0], p1y = p[1], p2x = p[2], p2y = p[3];
        float iw = fmaxf(fminf(p2x, t2x) - fmaxf(p1x, t1x), 0.f);
        float ih = fmaxf(fminf(p2y, t2y) - fmaxf(p1y, t1y), 0.f);
        float inter = iw * ih;
        float w1 = p2x - p1x, h1 = p2y - p1y;
        float w2 = t2x - t1x, h2 = t2y - t1y;
        float uni = w1 * h1 + w2 * h2 - inter + EPSF;
        float iou = inter / uni;
        // BCE target term: -x[tlab] * (iou * fg)
        const float* cls = br ? cls1 : cls0;
        int tlab = gl[b * MM + m];
        bce = -cls[(size_t)idx * NCLS + tlab] * iou;
        // CIoU (replicates reference bug: ch = max(p2y,t2y) - p1y)
        float cw = fmaxf(p2x, t2x) - fminf(p1x, t1x);
        float ch = fmaxf(p2y, t2y) - p1y;
        float c2 = cw * cw + ch * ch + EPSF;
        float dx = p1x + p2x - t1x - t2x;
        float dy = p1y + p2y - t1y - t2y;
        float rho2 = (dx * dx + dy * dy) * 0.25f;
        const float pi2 = 9.869604401089358f;
        float dv = atanf(w2 / (h2 + EPSF)) - atanf(w1 / (h1 + EPSF));
        float v  = (4.0f / pi2) * dv * dv;
        float alpha = v / (v - iou + (1.0f + EPSF));
        lbox = 1.0f - (iou - (rho2 / c2 + v * alpha));
        // DFL
        const float* regs = br ? reg1 : reg0;
        float s  = strides[n];
        float ax = anchors[2 * n], ay = anchors[2 * n + 1];
        float tt[4] = { (ax - t1x) / s, (ay - t1y) / s,
                        (t2x - ax) / s, (t2y - ay) / s };
        const float* r = regs + (size_t)idx * 64;
#pragma unroll
        for (int g = 0; g < 4; g++) {
            float v0 = fminf(fmaxf(tt[g], 0.f), 14.99f);
            int   tl = (int)v0;
            float wl = (float)(tl + 1) - v0;
            float wr = 1.0f - wl;
            float mx = -1e30f;
#pragma unroll
            for (int j = 0; j < RMv; j++) mx = fmaxf(mx, r[g * RMv + j]);
            float se = 0.f;
#pragma unroll
            for (int j = 0; j < RMv; j++) se += __expf(r[g * RMv + j] - mx);
            float lse = __logf(se) + mx;
            ldfl += -(r[g * RMv + tl]     - lse) * wl
                    -(r[g * RMv + tl + 1] - lse) * wr;
        }
    }
    float vals[4] = { bce, lbox, ldfl, np };
    __shared__ float sh[8];
#pragma unroll
    for (int q = 0; q < 4; q++) {
        float v = warpSum(vals[q]);
        if ((threadIdx.x & 31) == 0) sh[threadIdx.x >> 5] = v;
        __syncthreads();
        if (threadIdx.x < 8) {
            float w = sh[threadIdx.x];
#pragma unroll
            for (int o = 4; o > 0; o >>= 1) w += __shfl_down_sync(0xffu, w, o);
            if (threadIdx.x == 0 && w != 0.f) atomicAdd(&g_acc[br * 4 + q], (double)w);
        }
        __syncthreads();
    }
}

// ---------------- K5: finalize ---------------------------------------------------
__global__ void final_kernel(float* __restrict__ out) {
    double t[2], c[2], bx[2], df[2];
    for (int br = 0; br < 2; br++) {
        double bce  = g_acc[br * 4 + 0];
        double lbox = g_acc[br * 4 + 1];
        double ldfl = g_acc[br * 4 + 2];
        double nfg  = fmax(g_acc[br * 4 + 3], 1.0);
        c[br]  = bce / nfg;
        bx[br] = lbox / nfg;
        df[br] = ldfl / (nfg * 4.0);
        t[br]  = c[br] + bx[br] * 7.5 + df[br] * 1.5;
    }
    out[0] = (float)(t[0] + t[1]);
    out[1] = (float)(c[0] + c[1]);
    out[2] = (float)(bx[0] + bx[1]);
    out[3] = (float)(df[0] + df[1]);
    out[4] = (float)t[0];
    out[5] = (float)t[1];
}

// ---------------- launch -----------------------------------------------------------
extern "C" void kernel_launch(void* const* d_in, const int* in_sizes, int n_in,
                              void* d_out, int out_size) {
    const float* cls0    = (const float*)d_in[0];
    const float* reg0    = (const float*)d_in[1];
    const float* cls1    = (const float*)d_in[2];
    const float* reg1    = (const float*)d_in[3];
    const float* anchors = (const float*)d_in[4];
    const float* strides = (const float*)d_in[5];
    const int*   gl      = (const int*)d_in[6];
    const float* gb      = (const float*)d_in[7];
    const float* mg      = (const float*)d_in[8];
    float* out = (float*)d_out;

    decode_kernel<<<dim3((BN * 4 + 255) / 256, 2), 256>>>(reg0, reg1, anchors, strides);
    bce_gather_kernel<<<2048, 256>>>(cls0, cls1, gl);
    topk_fused_kernel<<<1024, 256>>>(anchors, gb, mg);
    loss_list_kernel<<<dim3((LISTMAX + 255) / 256, 2), 256>>>(cls0, cls1, reg0, reg1,
                                                              anchors, strides, gl, gb);
    final_kernel<<<1, 1>>>(out);
}